// round 15
// baseline (speedup 1.0000x reference)
#include <cuda_runtime.h>
#include <cstdint>
#include <math.h>

#define T_TOK 8192
#define D_DIM 7168
#define E_EXP 256
#define K_TOP 8
#define G_GRP 8
#define LG_GRP 4

#define BM 128
#define BN 128
#define BK 16
#define PAD 132   // padded smem row (floats) to dodge bank conflicts

__device__ float g_logits[(size_t)T_TOK * E_EXP];

// ---------------- packed f32x2 helpers ----------------
__device__ __forceinline__ uint64_t pack2(float lo, float hi) {
    uint64_t r;
    asm("mov.b64 %0, {%1, %2};" : "=l"(r) : "r"(__float_as_uint(lo)), "r"(__float_as_uint(hi)));
    return r;
}
__device__ __forceinline__ void ffma2(uint64_t& d, uint64_t a, uint64_t b) {
    asm("fma.rn.f32x2 %0, %1, %2, %0;" : "+l"(d) : "l"(a), "l"(b));
}
__device__ __forceinline__ float2 unpack2(uint64_t v) {
    uint32_t lo, hi;
    asm("mov.b64 {%0, %1}, %2;" : "=r"(lo), "=r"(hi) : "l"(v));
    float2 f; f.x = __uint_as_float(lo); f.y = __uint_as_float(hi);
    return f;
}

// ---------------- GEMM: byte-identical to R13 (session best) ----------------
__global__ __launch_bounds__(256, 1)
void gemm_kernel(const float* __restrict__ A,   // x [T, D]
                 const float* __restrict__ B,   // W [E, D]
                 float* __restrict__ C,         // logits [T, E]
                 void* __restrict__ cnt_out,
                 int mode)
{
    __shared__ float As[BK][PAD];
    __shared__ float Bs[BK][PAD];

    const int tid = threadIdx.x;

    // fold-in: zero the counts output region (route launches after this kernel)
    if (blockIdx.x == 0 && blockIdx.y == 0) {
        if (mode == 2) ((float*)cnt_out)[tid] = 0.0f;
        else           ((int*)cnt_out)[tid]   = 0;
    }

    const int tx = tid & 15;
    const int ty = tid >> 4;
    const int tile_n = blockIdx.x;
    const int tile_m = blockIdx.y;

    const float* Ab = A + (size_t)tile_m * BM * D_DIM;
    const float* Bb = B + (size_t)tile_n * BN * D_DIM;

    const int lr = tid >> 2;
    const int lc = (tid & 3) * 4;

    uint64_t acc[8][4];
    #pragma unroll
    for (int i = 0; i < 8; i++)
        #pragma unroll
        for (int j = 0; j < 4; j++) acc[i][j] = 0ull;

    float4 a0 = *(const float4*)(Ab + (size_t)lr * D_DIM + lc);
    float4 a1 = *(const float4*)(Ab + (size_t)(lr + 64) * D_DIM + lc);
    float4 b0 = *(const float4*)(Bb + (size_t)lr * D_DIM + lc);
    float4 b1 = *(const float4*)(Bb + (size_t)(lr + 64) * D_DIM + lc);

    for (int k0 = 0; k0 < D_DIM; k0 += BK) {
        __syncthreads();
        As[lc + 0][lr] = a0.x; As[lc + 1][lr] = a0.y; As[lc + 2][lr] = a0.z; As[lc + 3][lr] = a0.w;
        As[lc + 0][lr + 64] = a1.x; As[lc + 1][lr + 64] = a1.y; As[lc + 2][lr + 64] = a1.z; As[lc + 3][lr + 64] = a1.w;
        Bs[lc + 0][lr] = b0.x; Bs[lc + 1][lr] = b0.y; Bs[lc + 2][lr] = b0.z; Bs[lc + 3][lr] = b0.w;
        Bs[lc + 0][lr + 64] = b1.x; Bs[lc + 1][lr + 64] = b1.y; Bs[lc + 2][lr + 64] = b1.z; Bs[lc + 3][lr + 64] = b1.w;
        __syncthreads();

        const int kn = k0 + BK;
        if (kn < D_DIM) {
            a0 = *(const float4*)(Ab + (size_t)lr * D_DIM + kn + lc);
            a1 = *(const float4*)(Ab + (size_t)(lr + 64) * D_DIM + kn + lc);
            b0 = *(const float4*)(Bb + (size_t)lr * D_DIM + kn + lc);
            b1 = *(const float4*)(Bb + (size_t)(lr + 64) * D_DIM + kn + lc);
        }

        #pragma unroll
        for (int kk = 0; kk < BK; kk++) {
            float4 av0 = *(const float4*)&As[kk][ty * 8];
            float4 av1 = *(const float4*)&As[kk][ty * 8 + 4];
            float4 bv0 = *(const float4*)&Bs[kk][tx * 8];
            float4 bv1 = *(const float4*)&Bs[kk][tx * 8 + 4];
            uint64_t bp[4];
            bp[0] = pack2(bv0.x, bv0.y);
            bp[1] = pack2(bv0.z, bv0.w);
            bp[2] = pack2(bv1.x, bv1.y);
            bp[3] = pack2(bv1.z, bv1.w);
            float av[8] = {av0.x, av0.y, av0.z, av0.w, av1.x, av1.y, av1.z, av1.w};
            #pragma unroll
            for (int i = 0; i < 8; i++) {
                uint64_t ap = pack2(av[i], av[i]);
                #pragma unroll
                for (int j = 0; j < 4; j++) ffma2(acc[i][j], ap, bp[j]);
            }
        }
    }

    const int row0 = tile_m * BM + ty * 8;
    const int col0 = tile_n * BN + tx * 8;
    #pragma unroll
    for (int i = 0; i < 8; i++) {
        float2 c0 = unpack2(acc[i][0]);
        float2 c1 = unpack2(acc[i][1]);
        float2 c2 = unpack2(acc[i][2]);
        float2 c3 = unpack2(acc[i][3]);
        float* cp = C + (size_t)(row0 + i) * E_EXP + col0;
        *(float4*)(cp)     = make_float4(c0.x, c0.y, c1.x, c1.y);
        *(float4*)(cp + 4) = make_float4(c2.x, c2.y, c3.x, c3.y);
    }
}

// ---------------- Routing: ONE THREAD per token (scalar, no shuffles) ----------------
// jax top_k tie rule (lower index wins on equal values) is preserved by:
//  - group selection: ascending scan with strict '>' (earlier group wins ties)
//  - expert top-8: candidates processed in ascending index; a candidate is
//    beaten by kept element q iff kv[q] >= v (kept elements always have lower
//    index), so equal values keep the earlier index ranked higher.
__global__ __launch_bounds__(128)
void route_kernel(const float* __restrict__ logits,
                  const float* __restrict__ bias,
                  void* __restrict__ w_out,
                  void* __restrict__ idx_out,
                  void* __restrict__ cnt_out,
                  int mode)
{
    const float NEG_INF = __int_as_float(0xff800000);
    const int t = blockIdx.x * 128 + threadIdx.x;
    if (t >= T_TOK) return;

    const float* lp = logits + (size_t)t * E_EXP;

    // ---- pass 1: per-group top-2 of biased scores -> group scores ----
    float gsc[G_GRP];
    #pragma unroll
    for (int g = 0; g < G_GRP; g++) {
        float m1 = NEG_INF, m2 = NEG_INF;
        #pragma unroll
        for (int j = 0; j < 32; j += 4) {
            const float4 z4 = __ldg((const float4*)(lp + g * 32 + j));
            const float4 b4 = __ldg((const float4*)(bias + g * 32 + j));
            const float zz[4] = {z4.x, z4.y, z4.z, z4.w};
            const float bb[4] = {b4.x, b4.y, b4.z, b4.w};
            #pragma unroll
            for (int e = 0; e < 4; e++) {
                const float sig = 1.0f / (1.0f + expf(-zz[e]));
                const float v = sig + bb[e];
                const float hi = fmaxf(m1, v);
                m2 = fmaxf(m2, fminf(m1, v));
                m1 = hi;
            }
        }
        gsc[g] = m1 + m2;
    }

    // ---- top-LG groups (ties -> lower group index) ----
    unsigned chosen = 0;
    #pragma unroll
    for (int it = 0; it < LG_GRP; it++) {
        float best = NEG_INF; int bg = 0;
        #pragma unroll
        for (int g = 0; g < G_GRP; g++) {
            bool free_g = ((chosen >> g) & 1u) == 0u;
            if (free_g && gsc[g] > best) { best = gsc[g]; bg = g; }
        }
        chosen |= 1u << bg;
    }

    // ---- pass 2: top-8 experts via unrolled register insertion ----
    float kv[K_TOP], ks[K_TOP];
    int   ki[K_TOP];
    #pragma unroll
    for (int q = 0; q < K_TOP; q++) { kv[q] = NEG_INF; ks[q] = 0.0f; ki[q] = 0; }

    #pragma unroll
    for (int g = 0; g < G_GRP; g++) {
        const bool gsel = ((chosen >> g) & 1u) != 0u;
        #pragma unroll
        for (int j = 0; j < 32; j += 4) {
            const float4 z4 = __ldg((const float4*)(lp + g * 32 + j));
            const float4 b4 = __ldg((const float4*)(bias + g * 32 + j));
            const float zz[4] = {z4.x, z4.y, z4.z, z4.w};
            const float bb[4] = {b4.x, b4.y, b4.z, b4.w};
            #pragma unroll
            for (int e = 0; e < 4; e++) {
                const float sig = 1.0f / (1.0f + expf(-zz[e]));   // identical to pass 1
                const float v = gsel ? (sig + bb[e]) : NEG_INF;
                const int idx = g * 32 + j + e;
                // rank among kept (kv>= v means kept beats v; masked v=-inf is
                // beaten-by-all since kv initializes to -inf and -inf >= -inf)
                int p = 0;
                #pragma unroll
                for (int q = 0; q < K_TOP; q++) p += (kv[q] >= v) ? 1 : 0;
                // shift down and insert at p (static indices only; p==8 -> no-op)
                #pragma unroll
                for (int q = K_TOP - 1; q >= 1; q--) {
                    const bool sh = (q > p);
                    kv[q] = sh ? kv[q - 1] : kv[q];
                    ks[q] = sh ? ks[q - 1] : ks[q];
                    ki[q] = sh ? ki[q - 1] : ki[q];
                }
                #pragma unroll
                for (int q = 0; q < K_TOP; q++) {
                    const bool put = (q == p);
                    kv[q] = put ? v   : kv[q];
                    ks[q] = put ? sig : ks[q];
                    ki[q] = put ? idx : ki[q];
                }
            }
        }
    }

    // ---- normalize & write ----
    float wsum = 0.0f;
    #pragma unroll
    for (int k = 0; k < K_TOP; k++) wsum += ks[k];
    const float scale = 2.5f / wsum;

    const size_t o = (size_t)t * K_TOP;
    if (mode == 2) {      // all-float32 concatenated layout
        #pragma unroll
        for (int k = 0; k < K_TOP; k++) {
            ((float*)w_out)[o + k]   = ks[k] * scale;
            ((float*)idx_out)[o + k] = (float)ki[k];
            atomicAdd((float*)cnt_out + ki[k], 1.0f);
        }
    } else {              // byte-concat: f32 weights | i64 indices | i32 counts
        #pragma unroll
        for (int k = 0; k < K_TOP; k++) {
            ((float*)w_out)[o + k]       = ks[k] * scale;
            ((long long*)idx_out)[o + k] = (long long)ki[k];
            atomicAdd((int*)cnt_out + ki[k], 1);
        }
    }
}

// ---------------- launch ----------------
extern "C" void kernel_launch(void* const* d_in, const int* in_sizes, int n_in,
                              void* d_out, int out_size)
{
    const float* x    = (const float*)d_in[0];
    const float* W    = (const float*)d_in[1];
    const float* bias = (const float*)d_in[2];

    char* base = (char*)d_out;
    const size_t TK = (size_t)T_TOK * K_TOP;   // 65536

    int mode;
    void *w_out, *idx_out, *cnt_out;
    if (out_size == (int)(TK + TK + E_EXP)) {
        // 131328 elements: single-dtype f32 concat (JAX promotion, x64 off)
        mode = 2;
        w_out   = base;
        idx_out = base + TK * 4;
        cnt_out = base + 2 * TK * 4;
    } else {
        // byte-concatenated outputs: f32 weights | i64 indices | i32 counts
        mode = 0;
        w_out   = base;
        idx_out = base + TK * 4;
        cnt_out = base + TK * 4 + TK * 8;
    }

    dim3 grid(E_EXP / BN, T_TOK / BM);   // (2, 64) = 128 CTAs
    gemm_kernel<<<grid, 256>>>(x, W, g_logits, cnt_out, mode);

    route_kernel<<<T_TOK / 128, 128>>>(g_logits, bias, w_out, idx_out, cnt_out, mode);
}

// round 16
// speedup vs baseline: 1.1868x; 1.1868x over previous
#include <cuda_runtime.h>
#include <cstdint>
#include <math.h>

#define T_TOK 8192
#define D_DIM 7168
#define E_EXP 256
#define K_TOP 8
#define G_GRP 8
#define LG_GRP 4

#define BM 128
#define BN 128
#define BK 16
#define PAD 132   // padded smem row (floats) to dodge bank conflicts

__device__ float g_logits[(size_t)T_TOK * E_EXP];

// ---------------- packed f32x2 helpers ----------------
__device__ __forceinline__ uint64_t pack2(float lo, float hi) {
    uint64_t r;
    asm("mov.b64 %0, {%1, %2};" : "=l"(r) : "r"(__float_as_uint(lo)), "r"(__float_as_uint(hi)));
    return r;
}
__device__ __forceinline__ void ffma2(uint64_t& d, uint64_t a, uint64_t b) {
    asm("fma.rn.f32x2 %0, %1, %2, %0;" : "+l"(d) : "l"(a), "l"(b));
}
__device__ __forceinline__ float2 unpack2(uint64_t v) {
    uint32_t lo, hi;
    asm("mov.b64 {%0, %1}, %2;" : "=r"(lo), "=r"(hi) : "l"(v));
    float2 f; f.x = __uint_as_float(lo); f.y = __uint_as_float(hi);
    return f;
}

// ---------------- GEMM: C[t][e] = sum_k x[t][k] * W[e][k] ----------------
// Session-best (R13) kernel: R2's proven tile/fragment structure; CTA (0,0)
// zeroes the output counts region at start (route launches after this kernel).
__global__ __launch_bounds__(256, 1)
void gemm_kernel(const float* __restrict__ A,   // x [T, D]
                 const float* __restrict__ B,   // W [E, D]
                 float* __restrict__ C,         // logits [T, E]
                 void* __restrict__ cnt_out,
                 int mode)
{
    __shared__ float As[BK][PAD];
    __shared__ float Bs[BK][PAD];

    const int tid = threadIdx.x;

    // fold-in: zero the counts output region (one CTA, one store per thread)
    if (blockIdx.x == 0 && blockIdx.y == 0) {
        if (mode == 2) ((float*)cnt_out)[tid] = 0.0f;
        else           ((int*)cnt_out)[tid]   = 0;
    }

    const int tx = tid & 15;        // 0..15 -> col group (8 cols each)
    const int ty = tid >> 4;        // 0..15 -> row group (8 rows each)
    const int tile_n = blockIdx.x;  // 0..1   (E / BN)
    const int tile_m = blockIdx.y;  // 0..63  (T / BM)

    const float* Ab = A + (size_t)tile_m * BM * D_DIM;
    const float* Bb = B + (size_t)tile_n * BN * D_DIM;

    // global-load mapping: 2 rows x one float4 per thread, per matrix
    const int lr = tid >> 2;          // 0..63
    const int lc = (tid & 3) * 4;     // 0,4,8,12

    uint64_t acc[8][4];
    #pragma unroll
    for (int i = 0; i < 8; i++)
        #pragma unroll
        for (int j = 0; j < 4; j++) acc[i][j] = 0ull;

    // prefetch first tile
    float4 a0 = *(const float4*)(Ab + (size_t)lr * D_DIM + lc);
    float4 a1 = *(const float4*)(Ab + (size_t)(lr + 64) * D_DIM + lc);
    float4 b0 = *(const float4*)(Bb + (size_t)lr * D_DIM + lc);
    float4 b1 = *(const float4*)(Bb + (size_t)(lr + 64) * D_DIM + lc);

    for (int k0 = 0; k0 < D_DIM; k0 += BK) {
        __syncthreads();
        // transpose-store into smem: As[k][t], Bs[k][e]
        As[lc + 0][lr] = a0.x; As[lc + 1][lr] = a0.y; As[lc + 2][lr] = a0.z; As[lc + 3][lr] = a0.w;
        As[lc + 0][lr + 64] = a1.x; As[lc + 1][lr + 64] = a1.y; As[lc + 2][lr + 64] = a1.z; As[lc + 3][lr + 64] = a1.w;
        Bs[lc + 0][lr] = b0.x; Bs[lc + 1][lr] = b0.y; Bs[lc + 2][lr] = b0.z; Bs[lc + 3][lr] = b0.w;
        Bs[lc + 0][lr + 64] = b1.x; Bs[lc + 1][lr + 64] = b1.y; Bs[lc + 2][lr + 64] = b1.z; Bs[lc + 3][lr + 64] = b1.w;
        __syncthreads();

        // prefetch next tile (overlaps with compute below)
        const int kn = k0 + BK;
        if (kn < D_DIM) {
            a0 = *(const float4*)(Ab + (size_t)lr * D_DIM + kn + lc);
            a1 = *(const float4*)(Ab + (size_t)(lr + 64) * D_DIM + kn + lc);
            b0 = *(const float4*)(Bb + (size_t)lr * D_DIM + kn + lc);
            b1 = *(const float4*)(Bb + (size_t)(lr + 64) * D_DIM + kn + lc);
        }

        #pragma unroll
        for (int kk = 0; kk < BK; kk++) {
            float4 av0 = *(const float4*)&As[kk][ty * 8];
            float4 av1 = *(const float4*)&As[kk][ty * 8 + 4];
            float4 bv0 = *(const float4*)&Bs[kk][tx * 8];
            float4 bv1 = *(const float4*)&Bs[kk][tx * 8 + 4];
            uint64_t bp[4];
            bp[0] = pack2(bv0.x, bv0.y);
            bp[1] = pack2(bv0.z, bv0.w);
            bp[2] = pack2(bv1.x, bv1.y);
            bp[3] = pack2(bv1.z, bv1.w);
            float av[8] = {av0.x, av0.y, av0.z, av0.w, av1.x, av1.y, av1.z, av1.w};
            #pragma unroll
            for (int i = 0; i < 8; i++) {
                uint64_t ap = pack2(av[i], av[i]);
                #pragma unroll
                for (int j = 0; j < 4; j++) ffma2(acc[i][j], ap, bp[j]);
            }
        }
    }

    // epilogue: write 8x8 tile
    const int row0 = tile_m * BM + ty * 8;
    const int col0 = tile_n * BN + tx * 8;
    #pragma unroll
    for (int i = 0; i < 8; i++) {
        float2 c0 = unpack2(acc[i][0]);
        float2 c1 = unpack2(acc[i][1]);
        float2 c2 = unpack2(acc[i][2]);
        float2 c3 = unpack2(acc[i][3]);
        float4 v0 = make_float4(c0.x, c0.y, c1.x, c1.y);
        float4 v1 = make_float4(c2.x, c2.y, c3.x, c3.y);
        float* cp = C + (size_t)(row0 + i) * E_EXP + col0;
        *(float4*)(cp)     = v0;
        *(float4*)(cp + 4) = v1;
    }
}

// ---------------- Routing: one warp per token (proven, near latency floor) ----------------
__global__ __launch_bounds__(256)
void route_kernel(const float* __restrict__ logits,
                  const float* __restrict__ bias,
                  void* __restrict__ w_out,
                  void* __restrict__ idx_out,
                  void* __restrict__ cnt_out,
                  int mode)
{
    const float NEG_INF = __int_as_float(0xff800000);
    const int warp = threadIdx.x >> 5;
    const int lane = threadIdx.x & 31;
    const int t = blockIdx.x * 8 + warp;
    if (t >= T_TOK) return;

    const float* lp = logits + (size_t)t * E_EXP;

    float s[8];   // original sigmoid scores (used for weights)
    float v[8];   // biased scores (used for routing)
    #pragma unroll
    for (int r = 0; r < 8; r++) {
        float z = __ldg(lp + r * 32 + lane);
        float sig = 1.0f / (1.0f + expf(-z));
        s[r] = sig;
        v[r] = sig + __ldg(bias + r * 32 + lane);
    }

    // group scores: sum of top-2 biased scores per group (group r = reg r)
    float gsc[8];
    #pragma unroll
    for (int r = 0; r < 8; r++) {
        float m1 = v[r], m2 = NEG_INF;
        #pragma unroll
        for (int off = 16; off; off >>= 1) {
            float o1 = __shfl_xor_sync(0xffffffffu, m1, off);
            float o2 = __shfl_xor_sync(0xffffffffu, m2, off);
            float hi = fmaxf(m1, o1);
            float lo = fminf(m1, o1);
            m2 = fmaxf(lo, fmaxf(m2, o2));
            m1 = hi;
        }
        gsc[r] = m1 + m2;
    }

    // top-LG groups (ties -> lower group index, matching jax top_k)
    unsigned chosen = 0;
    #pragma unroll
    for (int it = 0; it < LG_GRP; it++) {
        float best = NEG_INF; int bg = 0;
        #pragma unroll
        for (int g = 0; g < G_GRP; g++) {
            bool free_g = ((chosen >> g) & 1u) == 0u;
            if (free_g && gsc[g] > best) { best = gsc[g]; bg = g; }
        }
        chosen |= 1u << bg;
    }
    #pragma unroll
    for (int r = 0; r < 8; r++)
        if (!((chosen >> r) & 1u)) v[r] = NEG_INF;

    // top-K experts, descending, ties -> lower expert index
    float my_w = 0.0f;
    int   my_e = 0;
    #pragma unroll
    for (int k = 0; k < K_TOP; k++) {
        float lb = NEG_INF; int lr = 0;
        #pragma unroll
        for (int r = 0; r < 8; r++)
            if (v[r] > lb) { lb = v[r]; lr = r; }
        float bv = lb;
        int be = lr * 32 + lane;
        #pragma unroll
        for (int off = 16; off; off >>= 1) {
            float ov = __shfl_xor_sync(0xffffffffu, bv, off);
            int   oe = __shfl_xor_sync(0xffffffffu, be, off);
            if (ov > bv || (ov == bv && oe < be)) { bv = ov; be = oe; }
        }
        const int wr = be >> 5, wl = be & 31;
        float sv_sel = 0.0f;
        #pragma unroll
        for (int r = 0; r < 8; r++)
            if (r == wr) sv_sel = s[r];
        float ws = __shfl_sync(0xffffffffu, sv_sel, wl);
        if (lane == k) { my_w = ws; my_e = be; }
        if (lane == wl) {
            #pragma unroll
            for (int r = 0; r < 8; r++)
                if (r == wr) v[r] = NEG_INF;
        }
    }

    // normalize: w = s / sum(s) * ROUTE_SCALE
    float wsum = (lane < K_TOP) ? my_w : 0.0f;
    #pragma unroll
    for (int off = 16; off; off >>= 1)
        wsum += __shfl_xor_sync(0xffffffffu, wsum, off);
    float wfin = my_w * (2.5f / wsum);

    if (lane < K_TOP) {
        const size_t o = (size_t)t * K_TOP + lane;
        if (mode == 2) {   // all-float32 concatenated layout
            ((float*)w_out)[o]   = wfin;
            ((float*)idx_out)[o] = (float)my_e;
            atomicAdd((float*)cnt_out + my_e, 1.0f);
        } else {           // byte-concatenated: f32 weights, i64 indices, i32 counts
            ((float*)w_out)[o]       = wfin;
            ((long long*)idx_out)[o] = (long long)my_e;
            atomicAdd((int*)cnt_out + my_e, 1);
        }
    }
}

// ---------------- launch ----------------
extern "C" void kernel_launch(void* const* d_in, const int* in_sizes, int n_in,
                              void* d_out, int out_size)
{
    const float* x    = (const float*)d_in[0];
    const float* W    = (const float*)d_in[1];
    const float* bias = (const float*)d_in[2];

    char* base = (char*)d_out;
    const size_t TK = (size_t)T_TOK * K_TOP;   // 65536

    int mode;
    void *w_out, *idx_out, *cnt_out;
    if (out_size == (int)(TK + TK + E_EXP)) {
        // 131328 elements: single-dtype f32 concat (JAX promotion, x64 off)
        mode = 2;
        w_out   = base;
        idx_out = base + TK * 4;
        cnt_out = base + 2 * TK * 4;
    } else {
        // byte-concatenated outputs: f32 weights | i64 indices | i32 counts
        mode = 0;
        w_out   = base;
        idx_out = base + TK * 4;
        cnt_out = base + TK * 4 + TK * 8;
    }

    dim3 grid(E_EXP / BN, T_TOK / BM);   // (2, 64) = 128 CTAs
    gemm_kernel<<<grid, 256>>>(x, W, g_logits, cnt_out, mode);

    route_kernel<<<T_TOK / 8, 256>>>(g_logits, bias, w_out, idx_out, cnt_out, mode);
}